// round 1
// baseline (speedup 1.0000x reference)
#include <cuda_runtime.h>

#define ADAM_B1 0.9f
#define ADAM_B2 0.999f
#define ADAM_EPS 1e-8f
#define ADAM_LR 0.02f

__global__ __launch_bounds__(128)
void pe_kernel(const float* __restrict__ X,     // (B,5,5)
               const float* __restrict__ Yg,    // (B,5)
               const float* __restrict__ ch0g,  // (B,1,3)
               const float* __restrict__ pf,    // (14,)
               const float* __restrict__ xag,   // (3,)
               const float* __restrict__ Sag,   // (3,3)
               const float* __restrict__ Seg,   // (5,5)
               const int*   __restrict__ nitp,  // scalar (may be null)
               float* __restrict__ out,         // (B,9)
               int B)
{
    int b = blockIdx.x * blockDim.x + threadIdx.x;
    if (b >= B) return;

    const float L[5] = {-0.275f, 0.025f, 0.5f, 0.70f, 1.15f};

    // ---- uniform (broadcast) parameters ----
    float p0=pf[0], p1=pf[1], p2=pf[2], p3=pf[3], p4=pf[4], p5=pf[5], p6=pf[6],
          p7=pf[7], p8=pf[8], p9=pf[9], p10=pf[10], p11=pf[11], p12=pf[12], p13=pf[13];

    float Aph[5], Acd[5], Bbs[5];
    #pragma unroll
    for (int l = 0; l < 5; l++) {
        Aph[l] = p0 * 0.05f * (1.0f + p1 * 0.1f * L[l] + p2 * 0.01f);
        Acd[l] = p5 * 0.1f * expf(-p6 * 1.7f * L[l]);
        Bbs[l] = p3 * 0.001f * (1.0f + p4 * 0.05f * L[l]);
    }
    const float cna = p12 * 0.005f;     // nap absorption coeff
    const float cnb = p13 * 0.005f;     // nap backscatter coeff
    const float c7  = p7 * 0.089f;
    const float c8  = p8 * 0.1245f;

    // symmetrize: d/dr of 0.5 * r^T S r is 0.5*(S+S^T) r
    float Se[5][5];
    #pragma unroll
    for (int i = 0; i < 5; i++)
        #pragma unroll
        for (int j = 0; j < 5; j++)
            Se[i][j] = 0.5f * (Seg[i*5 + j] + Seg[j*5 + i]);
    float Sa[3][3];
    #pragma unroll
    for (int i = 0; i < 3; i++)
        #pragma unroll
        for (int j = 0; j < 3; j++)
            Sa[i][j] = 0.5f * (Sag[i*3 + j] + Sag[j*3 + i]);
    float xa[3] = { xag[0], xag[1], xag[2] };

    // ---- per-pixel constants ----
    float fE[5], Y[5];
    #pragma unroll
    for (int l = 0; l < 5; l++) {
        float Edir = X[b*25 + l*5 + 0];
        float Edif = X[b*25 + l*5 + 1];
        fE[l] = (Edir + 0.5f * Edif) / (Edir + Edif);
        Y[l]  = Yg[b*5 + l];
    }

    float ch[3], m[3] = {0.f,0.f,0.f}, v[3] = {0.f,0.f,0.f};
    ch[0] = ch0g[b*3 + 0];
    ch[1] = ch0g[b*3 + 1];
    ch[2] = ch0g[b*3 + 2];

    // ---- iteration count (robust to int32 / int64-LE / float encodings) ----
    int iters = 50;
    if (nitp) {
        int it = *nitp;
        if (it >= 1 && it <= 100000000) {
            iters = it;
        } else {
            float f = __int_as_float(it);
            if (f >= 1.0f && f <= 1e8f) iters = (int)f;
        }
    }

    // ---- Adam loop, fully register-resident ----
    float b1t = 1.0f, b2t = 1.0f;
    for (int t = 0; t < iters; t++) {
        float chla = expf(ch[0]);
        float nap  = expf(ch[1]);
        float cdom = expf(ch[2]);

        float r[5], u[5], s[5];
        #pragma unroll
        for (int l = 0; l < 5; l++) {
            float a  = 0.0045f + Aph[l]*chla + Acd[l]*cdom + cna*nap;
            float bb = 0.0012f + Bbs[l]*chla + cnb*nap;
            float sv = a + bb;
            float uv = bb / sv;
            float rrs = (c7 + c8 * uv) * uv * fE[l];
            r[l] = rrs - Y[l];
            u[l] = uv;
            s[l] = sv;
        }

        // prior gradient: Sa_sym * (ch - xa)
        float d0 = ch[0]-xa[0], d1 = ch[1]-xa[1], d2 = ch[2]-xa[2];
        float g0 = Sa[0][0]*d0 + Sa[0][1]*d1 + Sa[0][2]*d2;
        float g1 = Sa[1][0]*d0 + Sa[1][1]*d1 + Sa[1][2]*d2;
        float g2 = Sa[2][0]*d0 + Sa[2][1]*d1 + Sa[2][2]*d2;

        // data gradient: sum_l (Se_sym r)_l * drrs/du * du/dch
        #pragma unroll
        for (int l = 0; l < 5; l++) {
            float w = Se[l][0]*r[0] + Se[l][1]*r[1] + Se[l][2]*r[2]
                    + Se[l][3]*r[3] + Se[l][4]*r[4];
            float dg = (c7 + 2.0f * c8 * u[l]) * fE[l];
            float q  = w * dg / s[l];
            float ul = u[l], om = 1.0f - ul;
            // a' and bb' wrt ch (chain through exp)
            float da0 = Aph[l]*chla, dbb0 = Bbs[l]*chla;
            float da1 = cna*nap,     dbb1 = cnb*nap;
            float da2 = Acd[l]*cdom;
            g0 += q * (om * dbb0 - ul * da0);
            g1 += q * (om * dbb1 - ul * da1);
            g2 += q * (-ul * da2);
        }

        // Adam (t starts at 1)
        b1t *= ADAM_B1;
        b2t *= ADAM_B2;
        float g[3] = { g0, g1, g2 };
        #pragma unroll
        for (int k = 0; k < 3; k++) {
            m[k] = ADAM_B1 * m[k] + (1.0f - ADAM_B1) * g[k];
            v[k] = ADAM_B2 * v[k] + (1.0f - ADAM_B2) * g[k] * g[k];
            float mh = m[k] / (1.0f - b1t);
            float vh = v[k] / (1.0f - b2t);
            ch[k] -= ADAM_LR * mh / (sqrtf(vh) + ADAM_EPS);
        }
    }

    // ---- outputs: [ch0, kd(5), bbp(3)] ----
    float chla = expf(ch[0]);
    float nap  = expf(ch[1]);
    float cdom = expf(ch[2]);
    float kfac = p9 * 0.9f + p10 * 0.1f;

    out[b*9 + 0] = ch[0];
    #pragma unroll
    for (int l = 0; l < 5; l++) {
        float a  = 0.0045f + Aph[l]*chla + Acd[l]*cdom + cna*nap;
        float bb = 0.0012f + Bbs[l]*chla + cnb*nap;
        float x3 = X[b*25 + l*5 + 3];
        float mu = 0.5f + 0.5f / (1.0f + expf(-x3));
        out[b*9 + 1 + l] = (a + bb) / mu * kfac;
    }
    const float L3[3] = {0.025f, 0.5f, 1.15f};
    #pragma unroll
    for (int j = 0; j < 3; j++) {
        float bbpv = p11 * (p3 * 0.001f * chla * (1.0f + p4 * 0.05f * L3[j]) + cnb * nap);
        out[b*9 + 6 + j] = bbpv;
    }
}

extern "C" void kernel_launch(void* const* d_in, const int* in_sizes, int n_in,
                              void* d_out, int out_size) {
    const float* X    = (const float*)d_in[0];
    const float* Y    = (const float*)d_in[1];
    const float* ch0  = (const float*)d_in[2];
    const float* pf   = (const float*)d_in[3];
    const float* xa   = (const float*)d_in[4];
    const float* Sa   = (const float*)d_in[5];
    const float* Se   = (const float*)d_in[6];
    const int*   nit  = (n_in >= 8) ? (const int*)d_in[7] : nullptr;
    float* out = (float*)d_out;

    int B = in_sizes[1] / 5;   // Y is (B,5)

    const int TPB = 128;
    int blocks = (B + TPB - 1) / TPB;
    pe_kernel<<<blocks, TPB>>>(X, Y, ch0, pf, xa, Sa, Se, nit, out, B);
}

// round 2
// speedup vs baseline: 1.7049x; 1.7049x over previous
#include <cuda_runtime.h>

#define ADAM_B1 0.9f
#define ADAM_B2 0.999f
#define ADAM_EPS 1e-8f
#define ADAM_LR 0.02f

__device__ __forceinline__ float sqrt_approx(float x) {
    float r;
    asm("sqrt.approx.f32 %0, %1;" : "=f"(r) : "f"(x));
    return r;
}
__device__ __forceinline__ float rcp_approx(float x) {
    float r;
    asm("rcp.approx.f32 %0, %1;" : "=f"(r) : "f"(x));
    return r;
}

__global__ __launch_bounds__(128, 6)
void pe_kernel(const float* __restrict__ X,     // (B,5,5)
               const float* __restrict__ Yg,    // (B,5)
               const float* __restrict__ ch0g,  // (B,1,3)
               const float* __restrict__ pf,    // (14,)
               const float* __restrict__ xag,   // (3,)
               const float* __restrict__ Sag,   // (3,3)
               const float* __restrict__ Seg,   // (5,5)
               const int*   __restrict__ nitp,  // scalar (may be null)
               float* __restrict__ out,         // (B,9)
               int B)
{
    int b = blockIdx.x * blockDim.x + threadIdx.x;
    if (b >= B) return;

    const float L[5] = {-0.275f, 0.025f, 0.5f, 0.70f, 1.15f};

    // ---- uniform (broadcast) parameters ----
    float p0=pf[0], p1=pf[1], p2=pf[2], p3=pf[3], p4=pf[4], p5=pf[5], p6=pf[6],
          p7=pf[7], p8=pf[8], p9=pf[9], p10=pf[10], p11=pf[11], p12=pf[12], p13=pf[13];

    float Aph[5], Acd[5], Bbs[5];
    #pragma unroll
    for (int l = 0; l < 5; l++) {
        Aph[l] = p0 * 0.05f * (1.0f + p1 * 0.1f * L[l] + p2 * 0.01f);
        Acd[l] = p5 * 0.1f * expf(-p6 * 1.7f * L[l]);   // uniform: keep accurate, once
        Bbs[l] = p3 * 0.001f * (1.0f + p4 * 0.05f * L[l]);
    }
    const float cna = p12 * 0.005f;     // nap absorption coeff
    const float cnb = p13 * 0.005f;     // nap backscatter coeff
    const float c7  = p7 * 0.089f;
    const float c8  = p8 * 0.1245f;

    // symmetrize: d/dr of 0.5 * r^T S r is 0.5*(S+S^T) r
    float Se[5][5];
    #pragma unroll
    for (int i = 0; i < 5; i++)
        #pragma unroll
        for (int j = 0; j < 5; j++)
            Se[i][j] = 0.5f * (Seg[i*5 + j] + Seg[j*5 + i]);
    float Sa[3][3];
    #pragma unroll
    for (int i = 0; i < 3; i++)
        #pragma unroll
        for (int j = 0; j < 3; j++)
            Sa[i][j] = 0.5f * (Sag[i*3 + j] + Sag[j*3 + i]);
    float xa[3] = { xag[0], xag[1], xag[2] };

    // ---- per-pixel constants ----
    float fE[5], Y[5];
    #pragma unroll
    for (int l = 0; l < 5; l++) {
        float Edir = X[b*25 + l*5 + 0];
        float Edif = X[b*25 + l*5 + 1];
        fE[l] = __fdividef(Edir + 0.5f * Edif, Edir + Edif);
        Y[l]  = Yg[b*5 + l];
    }

    float ch[3], m[3] = {0.f,0.f,0.f}, v[3] = {0.f,0.f,0.f};
    ch[0] = ch0g[b*3 + 0];
    ch[1] = ch0g[b*3 + 1];
    ch[2] = ch0g[b*3 + 2];

    // ---- iteration count (robust to int32 / int64-LE / float encodings) ----
    int iters = 50;
    if (nitp) {
        int it = *nitp;
        if (it >= 1 && it <= 100000000) {
            iters = it;
        } else {
            float f = __int_as_float(it);
            if (f >= 1.0f && f <= 1e8f) iters = (int)f;
        }
    }

    // ---- Adam loop, fully register-resident, approx transcendentals ----
    float b1t = 1.0f, b2t = 1.0f;
    for (int t = 0; t < iters; t++) {
        float chla = __expf(ch[0]);
        float nap  = __expf(ch[1]);
        float cdom = __expf(ch[2]);

        float da1  = cna * nap;   // nap absorption term (also d a/d ch1)
        float dbb1 = cnb * nap;   // nap backscatter term (also d bb/d ch1)

        float r[5], u[5], inv[5];
        #pragma unroll
        for (int l = 0; l < 5; l++) {
            float a  = 0.0045f + Aph[l]*chla + Acd[l]*cdom + da1;
            float bb = 0.0012f + Bbs[l]*chla + dbb1;
            float iv = rcp_approx(a + bb);
            float uv = bb * iv;
            float rrs = (c7 + c8 * uv) * uv * fE[l];
            r[l]   = rrs - Y[l];
            u[l]   = uv;
            inv[l] = iv;
        }

        // prior gradient: Sa_sym * (ch - xa)
        float d0 = ch[0]-xa[0], d1 = ch[1]-xa[1], d2 = ch[2]-xa[2];
        float g0 = Sa[0][0]*d0 + Sa[0][1]*d1 + Sa[0][2]*d2;
        float g1 = Sa[1][0]*d0 + Sa[1][1]*d1 + Sa[1][2]*d2;
        float g2 = Sa[2][0]*d0 + Sa[2][1]*d1 + Sa[2][2]*d2;

        // data gradient: sum_l (Se_sym r)_l * drrs/du * du/dch
        #pragma unroll
        for (int l = 0; l < 5; l++) {
            float w = Se[l][0]*r[0] + Se[l][1]*r[1] + Se[l][2]*r[2]
                    + Se[l][3]*r[3] + Se[l][4]*r[4];
            float dg = (c7 + 2.0f * c8 * u[l]) * fE[l];
            float q  = w * dg * inv[l];
            float ul = u[l], om = 1.0f - ul;
            float da0 = Aph[l]*chla, dbb0 = Bbs[l]*chla;
            float da2 = Acd[l]*cdom;
            g0 += q * (om * dbb0 - ul * da0);
            g1 += q * (om * dbb1 - ul * da1);
            g2 += q * (-ul * da2);
        }

        // Adam (t starts at 1)
        b1t *= ADAM_B1;
        b2t *= ADAM_B2;
        float invb1 = rcp_approx(1.0f - b1t);
        float invb2 = rcp_approx(1.0f - b2t);
        float g[3] = { g0, g1, g2 };
        #pragma unroll
        for (int k = 0; k < 3; k++) {
            m[k] = ADAM_B1 * m[k] + (1.0f - ADAM_B1) * g[k];
            v[k] = ADAM_B2 * v[k] + (1.0f - ADAM_B2) * g[k] * g[k];
            float mh = m[k] * invb1;
            float vh = v[k] * invb2;
            ch[k] -= ADAM_LR * mh * rcp_approx(sqrt_approx(vh) + ADAM_EPS);
        }
    }

    // ---- outputs: [ch0, kd(5), bbp(3)] ----
    float chla = __expf(ch[0]);
    float nap  = __expf(ch[1]);
    float cdom = __expf(ch[2]);
    float kfac = p9 * 0.9f + p10 * 0.1f;

    out[b*9 + 0] = ch[0];
    #pragma unroll
    for (int l = 0; l < 5; l++) {
        float a  = 0.0045f + Aph[l]*chla + Acd[l]*cdom + cna*nap;
        float bb = 0.0012f + Bbs[l]*chla + cnb*nap;
        float x3 = X[b*25 + l*5 + 3];
        float mu = 0.5f + 0.5f * rcp_approx(1.0f + __expf(-x3));
        out[b*9 + 1 + l] = (a + bb) * rcp_approx(mu) * kfac;
    }
    const float L3[3] = {0.025f, 0.5f, 1.15f};
    #pragma unroll
    for (int j = 0; j < 3; j++) {
        float bbpv = p11 * (p3 * 0.001f * chla * (1.0f + p4 * 0.05f * L3[j]) + cnb * nap);
        out[b*9 + 6 + j] = bbpv;
    }
}

extern "C" void kernel_launch(void* const* d_in, const int* in_sizes, int n_in,
                              void* d_out, int out_size) {
    const float* X    = (const float*)d_in[0];
    const float* Y    = (const float*)d_in[1];
    const float* ch0  = (const float*)d_in[2];
    const float* pf   = (const float*)d_in[3];
    const float* xa   = (const float*)d_in[4];
    const float* Sa   = (const float*)d_in[5];
    const float* Se   = (const float*)d_in[6];
    const int*   nit  = (n_in >= 8) ? (const int*)d_in[7] : nullptr;
    float* out = (float*)d_out;

    int B = in_sizes[1] / 5;   // Y is (B,5)

    const int TPB = 128;
    int blocks = (B + TPB - 1) / TPB;
    pe_kernel<<<blocks, TPB>>>(X, Y, ch0, pf, xa, Sa, Se, nit, out, B);
}